// round 2
// baseline (speedup 1.0000x reference)
#include <cuda_runtime.h>
#include <cuda_bf16.h>
#include <cstdint>

// ---------------------------------------------------------------------------
// Convolution_29738353557732 : e3nn-style graph conv
// inputs (metadata order):
//  0 node_input (N,160) f32   1 node_attr (N,1) f32   2 edge_attr (E,4) f32
//  3 edge_scalars (E,8) f32   4 sc_w0 (64,64)         5 sc_w1 (32,32)
//  6 lin1_w0 (64,64)          7 lin1_w1 (32,32)       8 fc_w1 (8,64)
//  9 fc_w2 (64,192)          10 lin2_w0 (96,64)      11 lin2_w1 (96,32)
// 12 lin3_w (96,1)           13 edge_src (E) i32     14 edge_dst (E) i32
// 15 num_neighbors (1) i32
// output: (N,160) f32
// ---------------------------------------------------------------------------

#define NMAX 50176

__device__ float g_f  [NMAX * 160];  // lin1 fctp of nodes (gathered on edges)
__device__ float g_sc [NMAX * 160];  // sc  fctp of nodes
__device__ float g_mid[NMAX * 384];  // segment-summed edge features

// ---------------------------------------------------------------- zero mid
__global__ void k_zero(int n4) {
    int i = blockIdx.x * 256 + threadIdx.x;
    if (i < n4) reinterpret_cast<float4*>(g_mid)[i] = make_float4(0.f, 0.f, 0.f, 0.f);
}

// ---------------------------------------------------------------- node pre
// warp per node: f_s/f_v (lin1) and sc_s/sc_v (sc) fctp, weights in smem.
__global__ __launch_bounds__(256) void k_nodepre(
    const float* __restrict__ x, const float* __restrict__ attr,
    const float* __restrict__ sc_w0, const float* __restrict__ sc_w1,
    const float* __restrict__ l1w0, const float* __restrict__ l1w1, int N)
{
    __shared__ float s_scw0[64 * 64], s_l1w0[64 * 64];
    __shared__ float s_scw1[32 * 32], s_l1w1[32 * 32];
    __shared__ float s_x[8][160];

    for (int i = threadIdx.x; i < 4096; i += 256) { s_scw0[i] = sc_w0[i]; s_l1w0[i] = l1w0[i]; }
    for (int i = threadIdx.x; i < 1024; i += 256) { s_scw1[i] = sc_w1[i]; s_l1w1[i] = l1w1[i]; }
    __syncthreads();

    int wid = threadIdx.x >> 5, l = threadIdx.x & 31;
    int nwarps = gridDim.x * 8;
    int w_[3], d_[3];
#pragma unroll
    for (int i = 0; i < 3; i++) { int o = l + 32 * i; w_[i] = o / 3; d_[i] = o - 3 * w_[i]; }

    for (int n = blockIdx.x * 8 + wid; n < N; n += nwarps) {
#pragma unroll
        for (int i = 0; i < 5; i++) s_x[wid][l + 32 * i] = x[(size_t)n * 160 + l + 32 * i];
        __syncwarp();
        float a = attr[n];

        float fs0 = 0.f, fs1 = 0.f, ss0 = 0.f, ss1 = 0.f;
#pragma unroll 8
        for (int u = 0; u < 64; u++) {
            float xu = s_x[wid][u];
            fs0 += xu * s_l1w0[u * 64 + l];
            fs1 += xu * s_l1w0[u * 64 + l + 32];
            ss0 += xu * s_scw0[u * 64 + l];
            ss1 += xu * s_scw0[u * 64 + l + 32];
        }
        float fv[3] = {0.f, 0.f, 0.f}, sv[3] = {0.f, 0.f, 0.f};
#pragma unroll 4
        for (int u = 0; u < 32; u++) {
#pragma unroll
            for (int i = 0; i < 3; i++) {
                float xv = s_x[wid][64 + 3 * u + d_[i]];
                fv[i] += xv * s_l1w1[u * 32 + w_[i]];
                sv[i] += xv * s_scw1[u * 32 + w_[i]];
            }
        }
        float* fo = &g_f[(size_t)n * 160];
        float* so = &g_sc[(size_t)n * 160];
        float S1 = 0.125f * a;                  // 1/sqrt(64)
        float S2 = 0.17677669529663687f * a;    // 1/sqrt(32)
        fo[l] = fs0 * S1;  fo[l + 32] = fs1 * S1;
        so[l] = ss0 * S1;  so[l + 32] = ss1 * S1;
#pragma unroll
        for (int i = 0; i < 3; i++) {
            fo[64 + l + 32 * i] = fv[i] * S2;
            so[64 + l + 32 * i] = sv[i] * S2;
        }
        __syncwarp();
    }
}

// ---------------------------------------------------------------- edge kernel
// Per 64-edge tile: MLP h = silu(es@fc_w1/sqrt8); weight = h@fc_w2/8 via
// f32x2-packed smem GEMM; then edge features + coalesced atomics into g_mid.
#define TILE_E 64
#define K2_SMEM 142080

__global__ __launch_bounds__(256, 1) void k_edge(
    const float* __restrict__ edge_attr, const float* __restrict__ edge_scalars,
    const float* __restrict__ fc_w1, const float* __restrict__ fc_w2,
    const int* __restrict__ edge_src, const int* __restrict__ edge_dst, int E)
{
    extern __shared__ unsigned char smem_raw[];
    float* s_w1 = reinterpret_cast<float*>(smem_raw);                 // 512
    float* s_w2 = s_w1 + 512;                                         // 12288
    unsigned long long* s_h2 = reinterpret_cast<unsigned long long*>(s_w2 + 12288); // 4096 u64
    float* s_wt = reinterpret_cast<float*>(s_h2 + 4096);              // 12288
    float* s_es = s_wt + 12288;                                       // 64*9
    float* s_ea = s_es + 576;                                         // 64*4
    int*   s_src = reinterpret_cast<int*>(s_ea + 256);                // 64
    int*   s_dst = s_src + 64;                                        // 64
    float* s_g  = reinterpret_cast<float*>(s_dst + 64);               // 8*160

    const int tid = threadIdx.x;
    for (int i = tid; i < 512;   i += 256) s_w1[i] = fc_w1[i];
    for (int i = tid; i < 12288; i += 256) s_w2[i] = fc_w2[i];
    __syncthreads();

    const int ntiles = (E + TILE_E - 1) / TILE_E;
    const int ty = tid >> 4, tx = tid & 15;
    const int ebase = ty * 4, k0 = tx * 12;
    const int wrp = tid >> 5, l = tid & 31;

    for (int tile = blockIdx.x; tile < ntiles; tile += gridDim.x) {
        const int e0 = tile * TILE_E;

        // ---- stage per-edge inputs
        for (int i = tid; i < 64 * 8; i += 256) {
            int e = i >> 3, c = i & 7, ge = e0 + e;
            s_es[e * 9 + c] = (ge < E) ? edge_scalars[(size_t)ge * 8 + c] : 0.f;
        }
        for (int i = tid; i < 64 * 4; i += 256) {
            int e = i >> 2, c = i & 3, ge = e0 + e;
            s_ea[e * 4 + c] = (ge < E) ? edge_attr[(size_t)ge * 4 + c] : 0.f;
        }
        if (tid < 64) {
            int ge = e0 + tid;
            s_src[tid] = (ge < E) ? edge_src[ge] : 0;
            s_dst[tid] = (ge < E) ? edge_dst[ge] : 0;
        }
        __syncthreads();

        // ---- phase 1: h = silu(es @ fc_w1 * 1/sqrt(8)), stored duplicated (f32x2)
        {
            int e = tid & 63, jg = tid >> 6;
            float es_[8];
#pragma unroll
            for (int c = 0; c < 8; c++) es_[c] = s_es[e * 9 + c];
#pragma unroll
            for (int jj = 0; jj < 16; jj++) {
                int j = jg * 16 + jj;
                float acc = 0.f;
#pragma unroll
                for (int c = 0; c < 8; c++) acc += es_[c] * s_w1[c * 64 + j];
                acc *= 0.3535533905932738f;
                float hval = acc / (1.f + __expf(-acc));
                unsigned long long p;
                asm("mov.b64 %0, {%1, %1};" : "=l"(p) : "f"(hval));
                s_h2[j * 64 + e] = p;
            }
        }
        __syncthreads();

        // ---- phase 2: weight = h @ fc_w2 * 0.125  (f32x2 GEMM, 4e x 12k per thread)
        {
            unsigned long long acc[4][6];
#pragma unroll
            for (int a = 0; a < 4; a++)
#pragma unroll
                for (int b = 0; b < 6; b++) acc[a][b] = 0ull;

#pragma unroll 8
            for (int j = 0; j < 64; j++) {
                const ulonglong2* hp = reinterpret_cast<const ulonglong2*>(&s_h2[j * 64 + ebase]);
                ulonglong2 ha = hp[0], hb = hp[1];
                unsigned long long av0 = ha.x, av1 = ha.y, av2 = hb.x, av3 = hb.y;
                const float* wrow = &s_w2[j * 192 + k0];
                ulonglong2 wA = *reinterpret_cast<const ulonglong2*>(wrow);
                ulonglong2 wB = *reinterpret_cast<const ulonglong2*>(wrow + 4);
                ulonglong2 wC = *reinterpret_cast<const ulonglong2*>(wrow + 8);
                unsigned long long bv[6] = {wA.x, wA.y, wB.x, wB.y, wC.x, wC.y};
#pragma unroll
                for (int ki = 0; ki < 6; ki++) {
                    asm("fma.rn.f32x2 %0, %1, %2, %0;" : "+l"(acc[0][ki]) : "l"(av0), "l"(bv[ki]));
                    asm("fma.rn.f32x2 %0, %1, %2, %0;" : "+l"(acc[1][ki]) : "l"(av1), "l"(bv[ki]));
                    asm("fma.rn.f32x2 %0, %1, %2, %0;" : "+l"(acc[2][ki]) : "l"(av2), "l"(bv[ki]));
                    asm("fma.rn.f32x2 %0, %1, %2, %0;" : "+l"(acc[3][ki]) : "l"(av3), "l"(bv[ki]));
                }
            }
#pragma unroll
            for (int ei = 0; ei < 4; ei++) {
                float* dstp = &s_wt[(ebase + ei) * 192 + k0];
#pragma unroll
                for (int ki = 0; ki < 6; ki++) {
                    float lo, hi;
                    asm("mov.b64 {%0, %1}, %2;" : "=f"(lo), "=f"(hi) : "l"(acc[ei][ki]));
                    dstp[2 * ki]     = lo * 0.125f;
                    dstp[2 * ki + 1] = hi * 0.125f;
                }
            }
        }
        __syncthreads();

        // ---- phase 3: edge features + coalesced atomic scatter (8 edges / warp)
        {
            float* gw = &s_g[wrp * 160];
            for (int ee = 0; ee < 8; ee++) {
                int e = wrp * 8 + ee;
                int ge = e0 + e;
                if (ge >= E) continue;   // warp-uniform
                int src = s_src[e], dst = s_dst[e];
                const float* frow = &g_f[(size_t)src * 160];
#pragma unroll
                for (int i = 0; i < 5; i++) gw[l + 32 * i] = frow[l + 32 * i];
                __syncwarp();

                float ys  = s_ea[e * 4 + 0];
                float yv0 = s_ea[e * 4 + 1];
                float yv1 = s_ea[e * 4 + 2];
                float yv2 = s_ea[e * 4 + 3];
                const float* wt = &s_wt[e * 192];
                float* mb = &g_mid[(size_t)dst * 384];

                // m0a : o in [0,64)
                atomicAdd(&mb[l],      gw[l]      * ys * wt[l]);
                atomicAdd(&mb[l + 32], gw[l + 32] * ys * wt[l + 32]);
                // m0b : o in [64,96)
                {
                    float dot = gw[64 + 3 * l] * yv0 + gw[64 + 3 * l + 1] * yv1
                              + gw[64 + 3 * l + 2] * yv2;
                    atomicAdd(&mb[64 + l], dot * 0.5773502691896258f * wt[160 + l]);
                }
                // m1a : o in [96,288)
#pragma unroll
                for (int i = 0; i < 6; i++) {
                    int t = l + 32 * i;
                    int u = t / 3, d = t - 3 * u;
                    float yvd = (d == 0) ? yv0 : ((d == 1) ? yv1 : yv2);
                    atomicAdd(&mb[96 + t], gw[u] * yvd * wt[64 + u]);
                }
                // m1b : o in [288,384)
#pragma unroll
                for (int i = 0; i < 3; i++) {
                    int t = l + 32 * i;
                    int u = t / 3;
                    atomicAdd(&mb[288 + t], gw[64 + t] * ys * wt[128 + u]);
                }
                __syncwarp();
            }
        }
        __syncthreads();
    }
}

// ---------------------------------------------------------------- node post
// warp per node: lin2 fctp on mid, angle, cos/sin gate, final output.
__global__ __launch_bounds__(128) void k_nodepost(
    const float* __restrict__ attr, const float* __restrict__ l2w0,
    const float* __restrict__ l2w1, const float* __restrict__ l3,
    const int* __restrict__ nn, float* __restrict__ out, int N)
{
    __shared__ float s_w0[96 * 64];
    __shared__ float s_w1[96 * 32];
    __shared__ float s_l3[96];
    __shared__ float s_mid[4][384];

    for (int i = threadIdx.x; i < 6144; i += 128) s_w0[i] = l2w0[i];
    for (int i = threadIdx.x; i < 3072; i += 128) s_w1[i] = l2w1[i];
    if (threadIdx.x < 96) s_l3[threadIdx.x] = l3[threadIdx.x];
    __syncthreads();

    float ms = rsqrtf((float)nn[0]);
    const float SC = 0.10206207261596575f; // 1/sqrt(96)
    int wrp = threadIdx.x >> 5, l = threadIdx.x & 31;
    int nwarps = gridDim.x * 4;
    int w_[3], d_[3];
#pragma unroll
    for (int i = 0; i < 3; i++) { int o = l + 32 * i; w_[i] = o / 3; d_[i] = o - 3 * w_[i]; }

    for (int n = blockIdx.x * 4 + wrp; n < N; n += nwarps) {
        const float* mrow = &g_mid[(size_t)n * 384];
#pragma unroll
        for (int i = 0; i < 12; i++) s_mid[wrp][l + 32 * i] = mrow[l + 32 * i];
        __syncwarp();
        float a = attr[n];

        float cs0 = 0.f, cs1 = 0.f, ang = 0.f;
#pragma unroll 8
        for (int u = 0; u < 96; u++) {
            float m = s_mid[wrp][u];
            cs0 += m * s_w0[u * 64 + l];
            cs1 += m * s_w0[u * 64 + l + 32];
            ang += m * s_l3[u];
        }
        float cv[3] = {0.f, 0.f, 0.f};
#pragma unroll 4
        for (int u = 0; u < 96; u++) {
            float m0 = s_mid[wrp][96 + 3 * u];
            float m1 = s_mid[wrp][96 + 3 * u + 1];
            float m2 = s_mid[wrp][96 + 3 * u + 2];
#pragma unroll
            for (int i = 0; i < 3; i++) {
                float mv = (d_[i] == 0) ? m0 : ((d_[i] == 1) ? m1 : m2);
                cv[i] += mv * s_w1[u * 32 + w_[i]];
            }
        }
        float sA = SC * ms * a;
        float angle = 0.1f * ang * sA;
        float sa, ca;
        sincosf(angle, &sa, &ca);

        const float* scrow = &g_sc[(size_t)n * 160];
        float* orow = &out[(size_t)n * 160];
        orow[l]      = ca * scrow[l]      + sa * (cs0 * sA);
        orow[l + 32] = ca * scrow[l + 32] + sa * (cs1 * sA);
#pragma unroll
        for (int i = 0; i < 3; i++)
            orow[64 + l + 32 * i] = ca * scrow[64 + l + 32 * i] + sa * (cv[i] * sA);
        __syncwarp();
    }
}

// ---------------------------------------------------------------- launch
extern "C" void kernel_launch(void* const* d_in, const int* in_sizes, int n_in,
                              void* d_out, int out_size)
{
    const float* node_input   = (const float*)d_in[0];
    const float* node_attr    = (const float*)d_in[1];
    const float* edge_attr    = (const float*)d_in[2];
    const float* edge_scalars = (const float*)d_in[3];
    const float* sc_w0        = (const float*)d_in[4];
    const float* sc_w1        = (const float*)d_in[5];
    const float* lin1_w0      = (const float*)d_in[6];
    const float* lin1_w1      = (const float*)d_in[7];
    const float* fc_w1        = (const float*)d_in[8];
    const float* fc_w2        = (const float*)d_in[9];
    const float* lin2_w0      = (const float*)d_in[10];
    const float* lin2_w1      = (const float*)d_in[11];
    const float* lin3_w       = (const float*)d_in[12];
    const int*   edge_src     = (const int*)d_in[13];
    const int*   edge_dst     = (const int*)d_in[14];
    const int*   num_neigh    = (const int*)d_in[15];
    float* out = (float*)d_out;

    int N = in_sizes[0] / 160;
    int E = in_sizes[2] / 4;

    // zero mid
    int n4 = N * 96;
    k_zero<<<(n4 + 255) / 256, 256>>>(n4);

    // node pre
    k_nodepre<<<(N + 7) / 8, 256>>>(node_input, node_attr, sc_w0, sc_w1,
                                    lin1_w0, lin1_w1, N);

    // edge kernel (dynamic smem > 48KB)
    cudaFuncSetAttribute(k_edge, cudaFuncAttributeMaxDynamicSharedMemorySize, K2_SMEM);
    k_edge<<<592, 256, K2_SMEM>>>(edge_attr, edge_scalars, fc_w1, fc_w2,
                                  edge_src, edge_dst, E);

    // node post
    k_nodepost<<<(N + 3) / 4, 128>>>(node_attr, lin2_w0, lin2_w1, lin3_w,
                                     num_neigh, out, N);
}

// round 3
// speedup vs baseline: 1.2127x; 1.2127x over previous
#include <cuda_runtime.h>
#include <cuda_bf16.h>
#include <cstdint>

// ---------------------------------------------------------------------------
// Convolution_29738353557732 : e3nn-style graph conv
// ---------------------------------------------------------------------------

#define NMAX 50176
typedef unsigned long long ull;

__device__ float g_f  [NMAX * 160];  // lin1 fctp of nodes (gathered on edges)
__device__ float g_sc [NMAX * 160];  // sc  fctp of nodes
__device__ float g_mid[NMAX * 384];  // segment-summed edge features

__device__ __forceinline__ void red4(float* p, float a, float b, float c, float d) {
    asm volatile("red.global.add.v4.f32 [%0], {%1,%2,%3,%4};"
                 :: "l"(p), "f"(a), "f"(b), "f"(c), "f"(d) : "memory");
}

// ---------------------------------------------------------------- node pre
// warp per node: f_s/f_v (lin1) and sc_s/sc_v (sc) fctp, weights in smem.
// Also zeroes g_mid (grid-stride) so no separate k_zero launch is needed.
__global__ __launch_bounds__(256) void k_nodepre(
    const float* __restrict__ x, const float* __restrict__ attr,
    const float* __restrict__ sc_w0, const float* __restrict__ sc_w1,
    const float* __restrict__ l1w0, const float* __restrict__ l1w1, int N)
{
    __shared__ float s_scw0[64 * 64], s_l1w0[64 * 64];
    __shared__ float s_scw1[32 * 32], s_l1w1[32 * 32];
    __shared__ float s_x[8][160];

    // zero g_mid
    {
        float4* m4 = reinterpret_cast<float4*>(g_mid);
        int tot = N * 96;
        int stride = gridDim.x * 256;
        for (int i = blockIdx.x * 256 + threadIdx.x; i < tot; i += stride)
            m4[i] = make_float4(0.f, 0.f, 0.f, 0.f);
    }

    for (int i = threadIdx.x; i < 4096; i += 256) { s_scw0[i] = sc_w0[i]; s_l1w0[i] = l1w0[i]; }
    for (int i = threadIdx.x; i < 1024; i += 256) { s_scw1[i] = sc_w1[i]; s_l1w1[i] = l1w1[i]; }
    __syncthreads();

    int wid = threadIdx.x >> 5, l = threadIdx.x & 31;
    int nwarps = gridDim.x * 8;
    int w_[3], d_[3];
#pragma unroll
    for (int i = 0; i < 3; i++) { int o = l + 32 * i; w_[i] = o / 3; d_[i] = o - 3 * w_[i]; }

    for (int n = blockIdx.x * 8 + wid; n < N; n += nwarps) {
#pragma unroll
        for (int i = 0; i < 5; i++) s_x[wid][l + 32 * i] = x[(size_t)n * 160 + l + 32 * i];
        __syncwarp();
        float a = attr[n];

        float fs0 = 0.f, fs1 = 0.f, ss0 = 0.f, ss1 = 0.f;
#pragma unroll 8
        for (int u = 0; u < 64; u++) {
            float xu = s_x[wid][u];
            fs0 += xu * s_l1w0[u * 64 + l];
            fs1 += xu * s_l1w0[u * 64 + l + 32];
            ss0 += xu * s_scw0[u * 64 + l];
            ss1 += xu * s_scw0[u * 64 + l + 32];
        }
        float fv[3] = {0.f, 0.f, 0.f}, sv[3] = {0.f, 0.f, 0.f};
#pragma unroll 4
        for (int u = 0; u < 32; u++) {
#pragma unroll
            for (int i = 0; i < 3; i++) {
                float xv = s_x[wid][64 + 3 * u + d_[i]];
                fv[i] += xv * s_l1w1[u * 32 + w_[i]];
                sv[i] += xv * s_scw1[u * 32 + w_[i]];
            }
        }
        float* fo = &g_f[(size_t)n * 160];
        float* so = &g_sc[(size_t)n * 160];
        float S1 = 0.125f * a;                  // 1/sqrt(64)
        float S2 = 0.17677669529663687f * a;    // 1/sqrt(32)
        fo[l] = fs0 * S1;  fo[l + 32] = fs1 * S1;
        so[l] = ss0 * S1;  so[l + 32] = ss1 * S1;
#pragma unroll
        for (int i = 0; i < 3; i++) {
            fo[64 + l + 32 * i] = fv[i] * S2;
            so[64 + l + 32 * i] = sv[i] * S2;
        }
        __syncwarp();
    }
}

// ---------------------------------------------------------------- edge kernel
// TILE_E=32, 2 blocks/SM. Phase 1: h=silu(es@fc_w1/sqrt8) stored duplicated
// (u64 {h,h}). Phase 2: weight = h@fc_w2*0.125 via f32x2 GEMM. Phase 3:
// prefetched f4 gather from g_f, edge features, red.global.add.v4 scatter.
#define TILE_E 32
#define K2_SMEM 99200

__global__ __launch_bounds__(256, 2) void k_edge(
    const float* __restrict__ edge_attr, const float* __restrict__ edge_scalars,
    const float* __restrict__ fc_w1, const float* __restrict__ fc_w2,
    const int* __restrict__ edge_src, const int* __restrict__ edge_dst, int E)
{
    extern __shared__ unsigned char smem_raw[];
    ull*   s_h  = reinterpret_cast<ull*>(smem_raw);        // 2048 u64 (16KB)
    float* s_w1 = reinterpret_cast<float*>(s_h + 2048);    // 512
    float* s_w2 = s_w1 + 512;                              // 12288 (48KB)
    float* s_wt = s_w2 + 12288;                            // 6144  (24KB)
    float* s_es = s_wt + 6144;                             // 32*9
    float* s_ea = s_es + 288;                              // 32*4
    int*   s_src = reinterpret_cast<int*>(s_ea + 128);     // 32
    int*   s_dst = s_src + 32;                             // 32
    float* s_g  = reinterpret_cast<float*>(s_dst + 32);    // 8*160 (5KB)

    const int tid = threadIdx.x;
    for (int i = tid; i < 512;   i += 256) s_w1[i] = fc_w1[i];
    for (int i = tid; i < 12288; i += 256) s_w2[i] = fc_w2[i];
    __syncthreads();

    const int ntiles = (E + TILE_E - 1) / TILE_E;
    const int wrp = tid >> 5, l = tid & 31;
    const int ebase = wrp * 4;       // phase-2: warp owns 4 edges
    const int k0 = l * 6;            // phase-2: lane owns 6 k

    ull SC8;
    asm("mov.b64 %0, {%1, %1};" : "=l"(SC8) : "f"(0.125f));

    for (int tile = blockIdx.x; tile < ntiles; tile += gridDim.x) {
        const int e0 = tile * TILE_E;

        // ---- stage per-edge inputs
        {
            if (tid < 256) {
                int e = tid >> 3, c = tid & 7, ge = e0 + e;
                s_es[e * 9 + c] = (ge < E) ? edge_scalars[(size_t)ge * 8 + c] : 0.f;
            }
            int i2 = tid - 0;
            if (i2 < 128) {
                int e = i2 >> 2, c = i2 & 3, ge = e0 + e;
                s_ea[e * 4 + c] = (ge < E) ? edge_attr[(size_t)ge * 4 + c] : 0.f;
            }
            if (tid < 32) {
                int ge = e0 + tid;
                s_src[tid] = (ge < E) ? edge_src[ge] : 0;
                s_dst[tid] = (ge < E) ? edge_dst[ge] : 0;
            }
        }
        __syncthreads();

        // ---- phase 1: h = silu(es @ fc_w1 / sqrt(8)), duplicated u64 {h,h}
        {
            int e = tid & 31, jg = tid >> 5;
            float es_[8];
#pragma unroll
            for (int c = 0; c < 8; c++) es_[c] = s_es[e * 9 + c];
#pragma unroll
            for (int jj = 0; jj < 8; jj++) {
                int j = jg * 8 + jj;
                float acc = 0.f;
#pragma unroll
                for (int c = 0; c < 8; c++) acc += es_[c] * s_w1[c * 64 + j];
                acc *= 0.3535533905932738f;
                float hval = acc / (1.f + __expf(-acc));
                ull p;
                asm("mov.b64 %0, {%1, %1};" : "=l"(p) : "f"(hval));
                s_h[j * 32 + e] = p;
            }
        }
        __syncthreads();

        // ---- phase 2: weight = h @ fc_w2 * 0.125  (f32x2 GEMM, 4e x 6k / thread)
        {
            ull acc[4][3];
#pragma unroll
            for (int a = 0; a < 4; a++)
#pragma unroll
                for (int b = 0; b < 3; b++) acc[a][b] = 0ull;

#pragma unroll 4
            for (int j = 0; j < 64; j++) {
                ull hp0 = s_h[j * 32 + ebase + 0];
                ull hp1 = s_h[j * 32 + ebase + 1];
                ull hp2 = s_h[j * 32 + ebase + 2];
                ull hp3 = s_h[j * 32 + ebase + 3];
                const ull* wp = reinterpret_cast<const ull*>(&s_w2[j * 192 + k0]);
                ull b0 = wp[0], b1 = wp[1], b2 = wp[2];
                asm("fma.rn.f32x2 %0, %1, %2, %0;" : "+l"(acc[0][0]) : "l"(hp0), "l"(b0));
                asm("fma.rn.f32x2 %0, %1, %2, %0;" : "+l"(acc[0][1]) : "l"(hp0), "l"(b1));
                asm("fma.rn.f32x2 %0, %1, %2, %0;" : "+l"(acc[0][2]) : "l"(hp0), "l"(b2));
                asm("fma.rn.f32x2 %0, %1, %2, %0;" : "+l"(acc[1][0]) : "l"(hp1), "l"(b0));
                asm("fma.rn.f32x2 %0, %1, %2, %0;" : "+l"(acc[1][1]) : "l"(hp1), "l"(b1));
                asm("fma.rn.f32x2 %0, %1, %2, %0;" : "+l"(acc[1][2]) : "l"(hp1), "l"(b2));
                asm("fma.rn.f32x2 %0, %1, %2, %0;" : "+l"(acc[2][0]) : "l"(hp2), "l"(b0));
                asm("fma.rn.f32x2 %0, %1, %2, %0;" : "+l"(acc[2][1]) : "l"(hp2), "l"(b1));
                asm("fma.rn.f32x2 %0, %1, %2, %0;" : "+l"(acc[2][2]) : "l"(hp2), "l"(b2));
                asm("fma.rn.f32x2 %0, %1, %2, %0;" : "+l"(acc[3][0]) : "l"(hp3), "l"(b0));
                asm("fma.rn.f32x2 %0, %1, %2, %0;" : "+l"(acc[3][1]) : "l"(hp3), "l"(b1));
                asm("fma.rn.f32x2 %0, %1, %2, %0;" : "+l"(acc[3][2]) : "l"(hp3), "l"(b2));
            }
#pragma unroll
            for (int ei = 0; ei < 4; ei++) {
                ull* outp = reinterpret_cast<ull*>(&s_wt[(ebase + ei) * 192 + k0]);
#pragma unroll
                for (int ki = 0; ki < 3; ki++) {
                    ull r;
                    asm("mul.rn.f32x2 %0, %1, %2;" : "=l"(r) : "l"(acc[ei][ki]), "l"(SC8));
                    outp[ki] = r;
                }
            }
        }
        __syncthreads();

        // ---- phase 3: prefetched gather + edge features + v4 atomic scatter
        {
            float* gw = &s_g[wrp * 160];
            float4* gw4 = reinterpret_cast<float4*>(gw);

            float4 pa, pb;
            {   // prefetch edge 0 of this warp
                int src = s_src[ebase];
                const float4* fr = reinterpret_cast<const float4*>(&g_f[(size_t)src * 160]);
                pa = fr[l];
                pb = (l < 8) ? fr[32 + l] : make_float4(0.f, 0.f, 0.f, 0.f);
            }

#pragma unroll
            for (int ee = 0; ee < 4; ee++) {
                const int e = ebase + ee;
                const int ge = e0 + e;
                const bool valid = (ge < E);

                gw4[l] = pa;
                if (l < 8) gw4[32 + l] = pb;
                if (ee < 3) {   // prefetch next edge (overlaps compute below)
                    int src = s_src[e + 1];
                    const float4* fr = reinterpret_cast<const float4*>(&g_f[(size_t)src * 160]);
                    pa = fr[l];
                    if (l < 8) pb = fr[32 + l];
                }
                __syncwarp();

                const float ys  = s_ea[e * 4 + 0];
                const float yv0 = s_ea[e * 4 + 1];
                const float yv1 = s_ea[e * 4 + 2];
                const float yv2 = s_ea[e * 4 + 3];
                const float* wt = &s_wt[e * 192];
                float* mb = &g_mid[(size_t)s_dst[e] * 384];

#pragma unroll
                for (int i = 0; i < 3; i++) {
                    const int t0 = i * 128 + 4 * l;
                    float v[4];
                    if (t0 < 64) {                       // m0a
#pragma unroll
                        for (int j = 0; j < 4; j++) v[j] = gw[t0 + j] * ys * wt[t0 + j];
                    } else if (t0 < 96) {                // m0b
                        const int c0 = t0 - 64;
#pragma unroll
                        for (int j = 0; j < 4; j++) {
                            int c = c0 + j;
                            float dot = gw[64 + 3 * c] * yv0 + gw[65 + 3 * c] * yv1
                                      + gw[66 + 3 * c] * yv2;
                            v[j] = dot * 0.5773502691896258f * wt[160 + c];
                        }
                    } else if (t0 < 288) {               // m1a
                        const int s0 = t0 - 96;
#pragma unroll
                        for (int j = 0; j < 4; j++) {
                            int s = s0 + j;
                            int u = s / 3, d = s - 3 * u;
                            float yvd = (d == 0) ? yv0 : ((d == 1) ? yv1 : yv2);
                            v[j] = gw[u] * yvd * wt[64 + u];
                        }
                    } else {                             // m1b
                        const int s0 = t0 - 288;
#pragma unroll
                        for (int j = 0; j < 4; j++) {
                            int s = s0 + j;
                            int u = s / 3;
                            v[j] = gw[64 + s] * ys * wt[128 + u];
                        }
                    }
                    if (valid) red4(&mb[t0], v[0], v[1], v[2], v[3]);
                }
                __syncwarp();
            }
        }
        __syncthreads();
    }
}

// ---------------------------------------------------------------- node post
// warp per node: lin2 fctp on mid, angle, cos/sin gate, final output.
__global__ __launch_bounds__(256) void k_nodepost(
    const float* __restrict__ attr, const float* __restrict__ l2w0,
    const float* __restrict__ l2w1, const float* __restrict__ l3,
    const int* __restrict__ nn, float* __restrict__ out, int N)
{
    __shared__ float s_w0[96 * 64];
    __shared__ float s_w1[96 * 32];
    __shared__ float s_l3[96];
    __shared__ float s_mid[8][384];

    for (int i = threadIdx.x; i < 6144; i += 256) s_w0[i] = l2w0[i];
    for (int i = threadIdx.x; i < 3072; i += 256) s_w1[i] = l2w1[i];
    if (threadIdx.x < 96) s_l3[threadIdx.x] = l3[threadIdx.x];
    __syncthreads();

    float ms = rsqrtf((float)nn[0]);
    const float SC = 0.10206207261596575f; // 1/sqrt(96)
    int wrp = threadIdx.x >> 5, l = threadIdx.x & 31;
    int nwarps = gridDim.x * 8;
    int w_[3], d_[3];
#pragma unroll
    for (int i = 0; i < 3; i++) { int o = l + 32 * i; w_[i] = o / 3; d_[i] = o - 3 * w_[i]; }

    for (int n = blockIdx.x * 8 + wrp; n < N; n += nwarps) {
        const float* mrow = &g_mid[(size_t)n * 384];
#pragma unroll
        for (int i = 0; i < 12; i++) s_mid[wrp][l + 32 * i] = mrow[l + 32 * i];
        __syncwarp();
        float a = attr[n];

        float cs0 = 0.f, cs1 = 0.f, ang = 0.f;
#pragma unroll 8
        for (int u = 0; u < 96; u++) {
            float m = s_mid[wrp][u];
            cs0 += m * s_w0[u * 64 + l];
            cs1 += m * s_w0[u * 64 + l + 32];
            ang += m * s_l3[u];
        }
        float cv[3] = {0.f, 0.f, 0.f};
#pragma unroll 4
        for (int u = 0; u < 96; u++) {
            float m0 = s_mid[wrp][96 + 3 * u];
            float m1 = s_mid[wrp][96 + 3 * u + 1];
            float m2 = s_mid[wrp][96 + 3 * u + 2];
#pragma unroll
            for (int i = 0; i < 3; i++) {
                float mv = (d_[i] == 0) ? m0 : ((d_[i] == 1) ? m1 : m2);
                cv[i] += mv * s_w1[u * 32 + w_[i]];
            }
        }
        float sA = SC * ms * a;
        float angle = 0.1f * ang * sA;
        float sa, ca;
        sincosf(angle, &sa, &ca);

        const float* scrow = &g_sc[(size_t)n * 160];
        float* orow = &out[(size_t)n * 160];
        orow[l]      = ca * scrow[l]      + sa * (cs0 * sA);
        orow[l + 32] = ca * scrow[l + 32] + sa * (cs1 * sA);
#pragma unroll
        for (int i = 0; i < 3; i++)
            orow[64 + l + 32 * i] = ca * scrow[64 + l + 32 * i] + sa * (cv[i] * sA);
        __syncwarp();
    }
}

// ---------------------------------------------------------------- launch
extern "C" void kernel_launch(void* const* d_in, const int* in_sizes, int n_in,
                              void* d_out, int out_size)
{
    const float* node_input   = (const float*)d_in[0];
    const float* node_attr    = (const float*)d_in[1];
    const float* edge_attr    = (const float*)d_in[2];
    const float* edge_scalars = (const float*)d_in[3];
    const float* sc_w0        = (const float*)d_in[4];
    const float* sc_w1        = (const float*)d_in[5];
    const float* lin1_w0      = (const float*)d_in[6];
    const float* lin1_w1      = (const float*)d_in[7];
    const float* fc_w1        = (const float*)d_in[8];
    const float* fc_w2        = (const float*)d_in[9];
    const float* lin2_w0      = (const float*)d_in[10];
    const float* lin2_w1      = (const float*)d_in[11];
    const float* lin3_w       = (const float*)d_in[12];
    const int*   edge_src     = (const int*)d_in[13];
    const int*   edge_dst     = (const int*)d_in[14];
    const int*   num_neigh    = (const int*)d_in[15];
    float* out = (float*)d_out;

    int N = in_sizes[0] / 160;
    int E = in_sizes[2] / 4;

    // node pre (also zeroes g_mid)
    k_nodepre<<<(N + 7) / 8, 256>>>(node_input, node_attr, sc_w0, sc_w1,
                                    lin1_w0, lin1_w1, N);

    // edge kernel: 2 blocks/SM persistent
    cudaFuncSetAttribute(k_edge, cudaFuncAttributeMaxDynamicSharedMemorySize, K2_SMEM);
    k_edge<<<296, 256, K2_SMEM>>>(edge_attr, edge_scalars, fc_w1, fc_w2,
                                  edge_src, edge_dst, E);

    // node post
    k_nodepost<<<(N + 7) / 8, 256>>>(node_attr, lin2_w0, lin2_w1, lin3_w,
                                     num_neigh, out, N);
}

// round 8
// speedup vs baseline: 1.2984x; 1.0707x over previous
#include <cuda_runtime.h>
#include <cuda_bf16.h>
#include <cstdint>

// ---------------------------------------------------------------------------
// Convolution_29738353557732 : e3nn-style graph conv
// R5: fp32 path. Phase-2 re-blocked (warp = 6 edges x 192 outs, k-pair f32x2),
// 2 CTAs/SM overlap, f32x2 node kernels.
// ---------------------------------------------------------------------------

#define NMAX 50176
typedef unsigned long long ull;

__device__ float g_f  [NMAX * 160];
__device__ float g_sc [NMAX * 160];
__device__ float g_mid[NMAX * 384];

__device__ __forceinline__ void red4(float* p, float a, float b, float c, float d) {
    asm volatile("red.global.add.v4.f32 [%0], {%1,%2,%3,%4};"
                 :: "l"(p), "f"(a), "f"(b), "f"(c), "f"(d) : "memory");
}
__device__ __forceinline__ ull fdup(float x) {
    ull r; asm("mov.b64 %0, {%1, %1};" : "=l"(r) : "f"(x)); return r;
}
__device__ __forceinline__ void ffma2(ull& acc, ull a, ull b) {
    asm("fma.rn.f32x2 %0, %1, %2, %0;" : "+l"(acc) : "l"(a), "l"(b));
}
__device__ __forceinline__ float2 funpack(ull p) {
    float lo, hi; asm("mov.b64 {%0, %1}, %2;" : "=f"(lo), "=f"(hi) : "l"(p));
    return make_float2(lo, hi);
}

// ---------------------------------------------------------------- node pre
// warp per node. Scalar outputs via f32x2 pairs (2l, 2l+1). Also zeroes g_mid.
__global__ __launch_bounds__(256) void k_nodepre(
    const float* __restrict__ x, const float* __restrict__ attr,
    const float* __restrict__ sc_w0, const float* __restrict__ sc_w1,
    const float* __restrict__ l1w0, const float* __restrict__ l1w1, int N)
{
    __shared__ float s_scw0[64 * 64], s_l1w0[64 * 64];
    __shared__ float s_scw1[32 * 32], s_l1w1[32 * 32];
    __shared__ float s_x[8][160];

    {   // zero g_mid
        float4* m4 = reinterpret_cast<float4*>(g_mid);
        int tot = N * 96;
        int stride = gridDim.x * 256;
        for (int i = blockIdx.x * 256 + threadIdx.x; i < tot; i += stride)
            m4[i] = make_float4(0.f, 0.f, 0.f, 0.f);
    }

    for (int i = threadIdx.x; i < 4096; i += 256) { s_scw0[i] = sc_w0[i]; s_l1w0[i] = l1w0[i]; }
    for (int i = threadIdx.x; i < 1024; i += 256) { s_scw1[i] = sc_w1[i]; s_l1w1[i] = l1w1[i]; }
    __syncthreads();

    int wid = threadIdx.x >> 5, l = threadIdx.x & 31;
    int nwarps = gridDim.x * 8;
    int w_[3], d_[3];
#pragma unroll
    for (int i = 0; i < 3; i++) { int o = l + 32 * i; w_[i] = o / 3; d_[i] = o - 3 * w_[i]; }

    for (int n = blockIdx.x * 8 + wid; n < N; n += nwarps) {
#pragma unroll
        for (int i = 0; i < 5; i++) s_x[wid][l + 32 * i] = x[(size_t)n * 160 + l + 32 * i];
        __syncwarp();
        float a = attr[n];

        // scalar part: outputs (2l, 2l+1) via f32x2
        ull af = 0ull, as = 0ull;
#pragma unroll 8
        for (int u = 0; u < 64; u++) {
            ull xd = fdup(s_x[wid][u]);
            ffma2(af, xd, *(const ull*)&s_l1w0[u * 64 + 2 * l]);
            ffma2(as, xd, *(const ull*)&s_scw0[u * 64 + 2 * l]);
        }
        float fv[3] = {0.f, 0.f, 0.f}, sv[3] = {0.f, 0.f, 0.f};
#pragma unroll 4
        for (int u = 0; u < 32; u++) {
#pragma unroll
            for (int i = 0; i < 3; i++) {
                float xv = s_x[wid][64 + 3 * u + d_[i]];
                fv[i] += xv * s_l1w1[u * 32 + w_[i]];
                sv[i] += xv * s_scw1[u * 32 + w_[i]];
            }
        }
        float* fo = &g_f[(size_t)n * 160];
        float* so = &g_sc[(size_t)n * 160];
        float S1 = 0.125f * a;
        float S2 = 0.17677669529663687f * a;
        float2 ff = funpack(af), ss = funpack(as);
        *(float2*)&fo[2 * l] = make_float2(ff.x * S1, ff.y * S1);
        *(float2*)&so[2 * l] = make_float2(ss.x * S1, ss.y * S1);
#pragma unroll
        for (int i = 0; i < 3; i++) {
            fo[64 + l + 32 * i] = fv[i] * S2;
            so[64 + l + 32 * i] = sv[i] * S2;
        }
        __syncwarp();
    }
}

// ---------------------------------------------------------------- edge kernel
// TILE_E=48, 256 threads, 2 CTAs/SM.
// phase1: h = silu(es@fc_w1/sqrt8) -> s_h[j][e]
// phase2: warp = 6 edges x 192 outs; lane k-pairs {2l, 2l+64, 2l+128}; w2
//         pre-scaled by 0.125. FFMA2 inner loop, h broadcast + dup.
// phase3: prefetched gather + features + red.v4 scatter (6 edges/warp).
#define TILE_E 48

#define O_H    0                    // 64*48*4      = 12288
#define O_W2   12288                // 12288 f      = 49152
#define O_WT   61440                // 48*192*4     = 36864
#define O_W1   98304                // 2048
#define O_ES   100352               // 48*9*4       = 1728
#define O_EA   102080               // 48*4*4       = 768
#define O_SRC  102848               // 192
#define O_DST  103040               // 192
#define O_G    103232               // 8*160*4      = 5120
#define K5_SMEM 108352

__global__ __launch_bounds__(256, 2) void k_edge(
    const float* __restrict__ edge_attr, const float* __restrict__ edge_scalars,
    const float* __restrict__ fc_w1, const float* __restrict__ fc_w2,
    const int* __restrict__ edge_src, const int* __restrict__ edge_dst, int E)
{
    extern __shared__ unsigned char sb[];
    float* s_h  = (float*)(sb + O_H);
    float* s_w2 = (float*)(sb + O_W2);
    float* s_wt = (float*)(sb + O_WT);
    float* s_w1 = (float*)(sb + O_W1);
    float* s_es = (float*)(sb + O_ES);
    float* s_ea = (float*)(sb + O_EA);
    int*   s_src = (int*)(sb + O_SRC);
    int*   s_dst = (int*)(sb + O_DST);
    float* s_g  = (float*)(sb + O_G);

    const int tid = threadIdx.x;
    const int wrp = tid >> 5, l = tid & 31;

    for (int i = tid; i < 512; i += 256) s_w1[i] = fc_w1[i];
    for (int i = tid; i < 12288; i += 256) s_w2[i] = fc_w2[i] * 0.125f;
    __syncthreads();

    const int ntiles = (E + TILE_E - 1) / TILE_E;
    const int eb = wrp * 6;   // phase-2/3 edge base for this warp

    for (int tile = blockIdx.x; tile < ntiles; tile += gridDim.x) {
        const int e0 = tile * TILE_E;

        // ---- stage per-edge inputs
        for (int i = tid; i < 48 * 8; i += 256) {
            int e = i >> 3, c = i & 7, ge = e0 + e;
            s_es[e * 9 + c] = (ge < E) ? edge_scalars[(size_t)ge * 8 + c] : 0.f;
        }
        if (tid < 192) {
            int e = tid >> 2, c = tid & 3, ge = e0 + e;
            s_ea[e * 4 + c] = (ge < E) ? edge_attr[(size_t)ge * 4 + c] : 0.f;
        }
        if (tid < 48) {
            int ge = e0 + tid;
            s_src[tid] = (ge < E) ? edge_src[ge] : 0;
            s_dst[tid] = (ge < E) ? edge_dst[ge] : 0;
        }
        __syncthreads();

        // ---- phase 1: h = silu(es @ fc_w1 / sqrt(8)) -> s_h[j*48+e]
        for (int i = tid; i < 48 * 64; i += 256) {
            int e = i % 48, j = i / 48;
            const float* es = &s_es[e * 9];
            float acc = 0.f;
#pragma unroll
            for (int c = 0; c < 8; c++) acc += es[c] * s_w1[c * 64 + j];
            acc *= 0.3535533905932738f;
            s_h[j * 48 + e] = acc / (1.f + __expf(-acc));
        }
        __syncthreads();

        // ---- phase 2: wt = h @ (0.125*w2); warp = 6 edges x 192 outs
        {
            ull acc[6][3];
#pragma unroll
            for (int a = 0; a < 6; a++)
#pragma unroll
                for (int b = 0; b < 3; b++) acc[a][b] = 0ull;

#pragma unroll 4
            for (int j = 0; j < 64; j++) {
                const float2* hp = (const float2*)&s_h[j * 48 + eb];
                float2 h01 = hp[0], h23 = hp[1], h45 = hp[2];
                ull hd[6];
                hd[0] = fdup(h01.x); hd[1] = fdup(h01.y);
                hd[2] = fdup(h23.x); hd[3] = fdup(h23.y);
                hd[4] = fdup(h45.x); hd[5] = fdup(h45.y);
                const ull* wp = (const ull*)&s_w2[j * 192 + 2 * l];
                ull w0 = wp[0], w1v = wp[32], w2v = wp[64];
#pragma unroll
                for (int e = 0; e < 6; e++) {
                    ffma2(acc[e][0], hd[e], w0);
                    ffma2(acc[e][1], hd[e], w1v);
                    ffma2(acc[e][2], hd[e], w2v);
                }
            }
#pragma unroll
            for (int e = 0; e < 6; e++) {
                ull* outp = (ull*)&s_wt[(eb + e) * 192 + 2 * l];
                outp[0]  = acc[e][0];
                outp[32] = acc[e][1];
                outp[64] = acc[e][2];
            }
        }
        __syncthreads();

        // ---- phase 3: prefetched gather + features + red.v4 scatter
        {
            float* gw = &s_g[wrp * 160];
            float4* gw4 = (float4*)gw;

            float4 pa, pb;
            {
                const float4* fr = (const float4*)&g_f[(size_t)s_src[eb] * 160];
                pa = fr[l];
                pb = (l < 8) ? fr[32 + l] : make_float4(0.f, 0.f, 0.f, 0.f);
            }

#pragma unroll
            for (int ee = 0; ee < 6; ee++) {
                const int e = eb + ee;
                const bool valid = (e0 + e) < E;

                gw4[l] = pa;
                if (l < 8) gw4[32 + l] = pb;
                if (ee < 5) {
                    const float4* fr = (const float4*)&g_f[(size_t)s_src[e + 1] * 160];
                    pa = fr[l];
                    if (l < 8) pb = fr[32 + l];
                }
                __syncwarp();

                const float ys  = s_ea[e * 4 + 0];
                const float yv0 = s_ea[e * 4 + 1];
                const float yv1 = s_ea[e * 4 + 2];
                const float yv2 = s_ea[e * 4 + 3];
                const float* wt = &s_wt[e * 192];
                float* mb = &g_mid[(size_t)s_dst[e] * 384];

#pragma unroll
                for (int i = 0; i < 3; i++) {
                    const int t0 = i * 128 + 4 * l;
                    float v[4];
                    if (t0 < 64) {                       // m0a
#pragma unroll
                        for (int j = 0; j < 4; j++) v[j] = gw[t0 + j] * ys * wt[t0 + j];
                    } else if (t0 < 96) {                // m0b
                        const int c0 = t0 - 64;
#pragma unroll
                        for (int j = 0; j < 4; j++) {
                            int c = c0 + j;
                            float dot = gw[64 + 3 * c] * yv0 + gw[65 + 3 * c] * yv1
                                      + gw[66 + 3 * c] * yv2;
                            v[j] = dot * 0.5773502691896258f * wt[160 + c];
                        }
                    } else if (t0 < 288) {               // m1a
                        const int s0 = t0 - 96;
#pragma unroll
                        for (int j = 0; j < 4; j++) {
                            int s = s0 + j;
                            int u = s / 3, d = s - 3 * u;
                            float yvd = (d == 0) ? yv0 : ((d == 1) ? yv1 : yv2);
                            v[j] = gw[u] * yvd * wt[64 + u];
                        }
                    } else {                             // m1b
                        const int s0 = t0 - 288;
#pragma unroll
                        for (int j = 0; j < 4; j++) {
                            int s = s0 + j;
                            int u = s / 3;
                            v[j] = gw[64 + s] * ys * wt[128 + u];
                        }
                    }
                    if (valid) red4(&mb[t0], v[0], v[1], v[2], v[3]);
                }
                __syncwarp();
            }
        }
        __syncthreads();
    }
}

// ---------------------------------------------------------------- node post
// warp per node; scalar part via f32x2 pairs (2l, 2l+1).
__global__ __launch_bounds__(256) void k_nodepost(
    const float* __restrict__ attr, const float* __restrict__ l2w0,
    const float* __restrict__ l2w1, const float* __restrict__ l3,
    const int* __restrict__ nn, float* __restrict__ out, int N)
{
    __shared__ float s_w0[96 * 64];
    __shared__ float s_w1[96 * 32];
    __shared__ float s_l3[96];
    __shared__ float s_mid[8][384];

    for (int i = threadIdx.x; i < 6144; i += 256) s_w0[i] = l2w0[i];
    for (int i = threadIdx.x; i < 3072; i += 256) s_w1[i] = l2w1[i];
    if (threadIdx.x < 96) s_l3[threadIdx.x] = l3[threadIdx.x];
    __syncthreads();

    float ms = rsqrtf((float)nn[0]);
    const float SC = 0.10206207261596575f;
    int wrp = threadIdx.x >> 5, l = threadIdx.x & 31;
    int nwarps = gridDim.x * 8;
    int w_[3], d_[3];
#pragma unroll
    for (int i = 0; i < 3; i++) { int o = l + 32 * i; w_[i] = o / 3; d_[i] = o - 3 * w_[i]; }

    for (int n = blockIdx.x * 8 + wrp; n < N; n += nwarps) {
        const float* mrow = &g_mid[(size_t)n * 384];
#pragma unroll
        for (int i = 0; i < 12; i++) s_mid[wrp][l + 32 * i] = mrow[l + 32 * i];
        __syncwarp();
        float a = attr[n];

        ull accc = 0ull;
        float ang = 0.f;
#pragma unroll 8
        for (int u = 0; u < 96; u++) {
            float m = s_mid[wrp][u];
            ffma2(accc, fdup(m), *(const ull*)&s_w0[u * 64 + 2 * l]);
            ang += m * s_l3[u];
        }
        float cv[3] = {0.f, 0.f, 0.f};
#pragma unroll 4
        for (int u = 0; u < 96; u++) {
            float m0 = s_mid[wrp][96 + 3 * u];
            float m1 = s_mid[wrp][96 + 3 * u + 1];
            float m2 = s_mid[wrp][96 + 3 * u + 2];
#pragma unroll
            for (int i = 0; i < 3; i++) {
                float mv = (d_[i] == 0) ? m0 : ((d_[i] == 1) ? m1 : m2);
                cv[i] += mv * s_w1[u * 32 + w_[i]];
            }
        }
        float sA = SC * ms * a;
        float angle = 0.1f * ang * sA;
        float sa, ca;
        sincosf(angle, &sa, &ca);

        const float* scrow = &g_sc[(size_t)n * 160];
        float* orow = &out[(size_t)n * 160];
        float2 cc = funpack(accc);
        float2 sc2 = *(const float2*)&scrow[2 * l];
        *(float2*)&orow[2 * l] = make_float2(ca * sc2.x + sa * (cc.x * sA),
                                             ca * sc2.y + sa * (cc.y * sA));
#pragma unroll
        for (int i = 0; i < 3; i++)
            orow[64 + l + 32 * i] = ca * scrow[64 + l + 32 * i] + sa * (cv[i] * sA);
        __syncwarp();
    }
}

// ---------------------------------------------------------------- launch
extern "C" void kernel_launch(void* const* d_in, const int* in_sizes, int n_in,
                              void* d_out, int out_size)
{
    const float* node_input   = (const float*)d_in[0];
    const float* node_attr    = (const float*)d_in[1];
    const float* edge_attr    = (const float*)d_in[2];
    const float* edge_scalars = (const float*)d_in[3];
    const float* sc_w0        = (const float*)d_in[4];
    const float* sc_w1        = (const float*)d_in[5];
    const float* lin1_w0      = (const float*)d_in[6];
    const float* lin1_w1      = (const float*)d_in[7];
    const float* fc_w1        = (const float*)d_in[8];
    const float* fc_w2        = (const float*)d_in[9];
    const float* lin2_w0      = (const float*)d_in[10];
    const float* lin2_w1      = (const float*)d_in[11];
    const float* lin3_w       = (const float*)d_in[12];
    const int*   edge_src     = (const int*)d_in[13];
    const int*   edge_dst     = (const int*)d_in[14];
    const int*   num_neigh    = (const int*)d_in[15];
    float* out = (float*)d_out;

    int N = in_sizes[0] / 160;
    int E = in_sizes[2] / 4;

    k_nodepre<<<(N + 7) / 8, 256>>>(node_input, node_attr, sc_w0, sc_w1,
                                    lin1_w0, lin1_w1, N);

    cudaFuncSetAttribute(k_edge, cudaFuncAttributeMaxDynamicSharedMemorySize, K5_SMEM);
    k_edge<<<296, 256, K5_SMEM>>>(edge_attr, edge_scalars, fc_w1, fc_w2,
                                  edge_src, edge_dst, E);

    k_nodepost<<<(N + 7) / 8, 256>>>(node_attr, lin2_w0, lin2_w1, lin3_w,
                                     num_neigh, out, N);
}